// round 7
// baseline (speedup 1.0000x reference)
#include <cuda_runtime.h>
#include <cuda_fp16.h>

#define NB 8192
#define FD 4096
#define NH 16
#define HI 256
#define HO 1024
#define MD 16384

// Scratch (device globals — no allocation in kernel_launch)
__device__ __half g_xperm[NB * FD];                 // 64 MB, x permuted+fp16
__device__ __half g_w1[NH * HI * HO];               // 8 MB
__device__ __half g_w2[NH * HO * HI];               // 8 MB
__device__ __half g_h[(long long)NB * MD];          // 256 MB, gelu(up) in fp16

__device__ __forceinline__ float gelu_f(float v) {
    return 0.5f * v * (1.0f + erff(v * 0.7071067811865476f));
}

__device__ __forceinline__ void ldsm4(unsigned &r0, unsigned &r1, unsigned &r2, unsigned &r3, unsigned addr) {
    asm volatile("ldmatrix.sync.aligned.m8n8.x4.shared.b16 {%0,%1,%2,%3},[%4];"
                 : "=r"(r0), "=r"(r1), "=r"(r2), "=r"(r3) : "r"(addr));
}
__device__ __forceinline__ void ldsm4t(unsigned &r0, unsigned &r1, unsigned &r2, unsigned &r3, unsigned addr) {
    asm volatile("ldmatrix.sync.aligned.m8n8.x4.trans.shared.b16 {%0,%1,%2,%3},[%4];"
                 : "=r"(r0), "=r"(r1), "=r"(r2), "=r"(r3) : "r"(addr));
}
__device__ __forceinline__ void mma16816(float c[4], const unsigned a[4], const unsigned b[2]) {
    asm volatile("mma.sync.aligned.m16n8k16.row.col.f32.f16.f16.f32 "
                 "{%0,%1,%2,%3},{%4,%5,%6,%7},{%8,%9},{%0,%1,%2,%3};"
                 : "+f"(c[0]), "+f"(c[1]), "+f"(c[2]), "+f"(c[3])
                 : "r"(a[0]), "r"(a[1]), "r"(a[2]), "r"(a[3]), "r"(b[0]), "r"(b[1]));
}

// ---------------------------------------------------------------------------
// Prep: gather-permute x into fp16; convert weights to fp16.
// perm is chunk-structured (64-contiguous): perm[k4..k4+3] are contiguous and
// perm[k4] % 4 == k4 % 4, so float4 loads stay aligned.
// ---------------------------------------------------------------------------
__global__ void __launch_bounds__(256) k_prep_x(const float* __restrict__ x,
                                                const int* __restrict__ perm) {
    int i = blockIdx.x * 256 + threadIdx.x;
    if (i >= NB * FD / 4) return;
    int b  = i >> 10;            // FD/4 = 1024 quads per row
    int k4 = (i & 1023) << 2;
    int p  = __ldg(perm + k4);
    const float4 v = *(const float4*)(x + (long long)b * FD + p);
    __half2* dst = (__half2*)(g_xperm + (long long)b * FD + k4);
    dst[0] = __floats2half2_rn(v.x, v.y);
    dst[1] = __floats2half2_rn(v.z, v.w);
}

__global__ void __launch_bounds__(256) k_prep_w(const float* __restrict__ wu,
                                                const float* __restrict__ wd) {
    int i = blockIdx.x * 256 + threadIdx.x;
    const int N4 = NH * HI * HO / 4;
    if (i >= N4) return;
    float4 a = *(const float4*)(wu + (long long)i * 4);
    __half2* d1 = (__half2*)(g_w1 + (long long)i * 4);
    d1[0] = __floats2half2_rn(a.x, a.y);
    d1[1] = __floats2half2_rn(a.z, a.w);
    float4 b = *(const float4*)(wd + (long long)i * 4);
    __half2* d2 = (__half2*)(g_w2 + (long long)i * 4);
    d2[0] = __floats2half2_rn(b.x, b.y);
    d2[1] = __floats2half2_rn(b.z, b.w);
}

// ---------------------------------------------------------------------------
// GEMM1: H = gelu(Xperm_head @ W1_head + b_up), fp16 out to g_h
// grid: x = head*8 + ntile (128), y = row tile (64). 256 threads, 8 warps 4x2.
// BM=128, BN=128, BK=32. K = HI = 256.
// ---------------------------------------------------------------------------
__global__ void __launch_bounds__(256) k_up(const float* __restrict__ b_up) {
    const int h  = blockIdx.x >> 3;
    const int nt = blockIdx.x & 7;
    const int r0 = blockIdx.y << 7;
    const int n0 = nt << 7;

    __shared__ __half As[128][40];   // pad 8 halves -> conflict-free ldmatrix
    __shared__ __half Bs[32][136];

    const int tid = threadIdx.x;
    const int lane = tid & 31, warp = tid >> 5;
    const int wm = warp & 3, wn = warp >> 2;

    const __half* Ag = g_xperm + (long long)r0 * FD + h * HI;
    const __half* Bg = g_w1 + (long long)h * HI * HO + n0;

    const int c0 = tid * 2, c1 = tid * 2 + 1;
    const int a_r0 = c0 >> 2, a_k0 = (c0 & 3) << 3;
    const int a_r1 = c1 >> 2, a_k1 = (c1 & 3) << 3;
    const int b_r0 = c0 >> 4, b_n0 = (c0 & 15) << 3;
    const int b_r1 = c1 >> 4, b_n1 = (c1 & 15) << 3;

    float acc[2][8][4];
#pragma unroll
    for (int i = 0; i < 2; i++)
#pragma unroll
        for (int j = 0; j < 8; j++)
#pragma unroll
            for (int k = 0; k < 4; k++) acc[i][j][k] = 0.f;

    unsigned as_base = (unsigned)__cvta_generic_to_shared(&As[0][0]);
    unsigned bs_base = (unsigned)__cvta_generic_to_shared(&Bs[0][0]);

    uint4 va0, va1, vb0, vb1;
    va0 = *(const uint4*)(Ag + (long long)a_r0 * FD + a_k0);
    va1 = *(const uint4*)(Ag + (long long)a_r1 * FD + a_k1);
    vb0 = *(const uint4*)(Bg + (long long)b_r0 * HO + b_n0);
    vb1 = *(const uint4*)(Bg + (long long)b_r1 * HO + b_n1);
    *(uint4*)(&As[a_r0][a_k0]) = va0;
    *(uint4*)(&As[a_r1][a_k1]) = va1;
    *(uint4*)(&Bs[b_r0][b_n0]) = vb0;
    *(uint4*)(&Bs[b_r1][b_n1]) = vb1;
    __syncthreads();

    const int KT = HI / 32;  // 8
    for (int kt = 0; kt < KT; kt++) {
        if (kt + 1 < KT) {
            va0 = *(const uint4*)(Ag + (long long)a_r0 * FD + (kt + 1) * 32 + a_k0);
            va1 = *(const uint4*)(Ag + (long long)a_r1 * FD + (kt + 1) * 32 + a_k1);
            vb0 = *(const uint4*)(Bg + (long long)((kt + 1) * 32 + b_r0) * HO + b_n0);
            vb1 = *(const uint4*)(Bg + (long long)((kt + 1) * 32 + b_r1) * HO + b_n1);
        }
#pragma unroll
        for (int ks = 0; ks < 2; ks++) {
            unsigned af[2][4];
#pragma unroll
            for (int mi = 0; mi < 2; mi++) {
                unsigned addr = as_base +
                    (((wm * 32 + mi * 16 + (lane & 15)) * 40 + ks * 16 + ((lane >> 4) << 3)) << 1);
                ldsm4(af[mi][0], af[mi][1], af[mi][2], af[mi][3], addr);
            }
            unsigned bf[8][2];
#pragma unroll
            for (int nj = 0; nj < 4; nj++) {
                unsigned addr = bs_base +
                    (((ks * 16 + (lane & 15)) * 136 + wn * 64 + nj * 16 + ((lane >> 4) << 3)) << 1);
                unsigned t0, t1, t2, t3;
                ldsm4t(t0, t1, t2, t3, addr);
                bf[nj * 2][0] = t0; bf[nj * 2][1] = t1;
                bf[nj * 2 + 1][0] = t2; bf[nj * 2 + 1][1] = t3;
            }
#pragma unroll
            for (int mi = 0; mi < 2; mi++)
#pragma unroll
                for (int ni = 0; ni < 8; ni++)
                    mma16816(acc[mi][ni], af[mi], bf[ni]);
        }
        __syncthreads();
        if (kt + 1 < KT) {
            *(uint4*)(&As[a_r0][a_k0]) = va0;
            *(uint4*)(&As[a_r1][a_k1]) = va1;
            *(uint4*)(&Bs[b_r0][b_n0]) = vb0;
            *(uint4*)(&Bs[b_r1][b_n1]) = vb1;
            __syncthreads();
        }
    }

    // Epilogue: +b_up, exact gelu, fp16 store
    const int g = lane >> 2, t = lane & 3;
#pragma unroll
    for (int mi = 0; mi < 2; mi++) {
#pragma unroll
        for (int ni = 0; ni < 8; ni++) {
            int r = r0 + wm * 32 + mi * 16 + g;
            int c = n0 + wn * 64 + ni * 8 + t * 2;
            float bu0 = __ldg(b_up + h * HO + c);
            float bu1 = __ldg(b_up + h * HO + c + 1);
            float v0 = gelu_f(acc[mi][ni][0] + bu0);
            float v1 = gelu_f(acc[mi][ni][1] + bu1);
            *(__half2*)(g_h + (long long)r * MD + h * HO + c) = __floats2half2_rn(v0, v1);
            v0 = gelu_f(acc[mi][ni][2] + bu0);
            v1 = gelu_f(acc[mi][ni][3] + bu1);
            *(__half2*)(g_h + (long long)(r + 8) * MD + h * HO + c) = __floats2half2_rn(v0, v1);
        }
    }
}

// ---------------------------------------------------------------------------
// GEMM2: out[:, perm[j]] = H_head @ W2_head + b_down[j]   (fp32 out, scattered)
// grid: x = head*2 + ntile (32), y = row tile (64). K = HO = 1024.
// perm chunk structure: j even => perm[j+1] == perm[j]+1 => float2 stores OK.
// ---------------------------------------------------------------------------
__global__ void __launch_bounds__(256) k_down(const int* __restrict__ perm,
                                              const float* __restrict__ b_down,
                                              float* __restrict__ out) {
    const int h  = blockIdx.x >> 1;
    const int nt = blockIdx.x & 1;
    const int r0 = blockIdx.y << 7;
    const int n0 = nt << 7;

    __shared__ __half As[128][40];
    __shared__ __half Bs[32][136];

    const int tid = threadIdx.x;
    const int lane = tid & 31, warp = tid >> 5;
    const int wm = warp & 3, wn = warp >> 2;

    const __half* Ag = g_h + (long long)r0 * MD + h * HO;
    const __half* Bg = g_w2 + (long long)h * HO * HI + n0;

    const int c0 = tid * 2, c1 = tid * 2 + 1;
    const int a_r0 = c0 >> 2, a_k0 = (c0 & 3) << 3;
    const int a_r1 = c1 >> 2, a_k1 = (c1 & 3) << 3;
    const int b_r0 = c0 >> 4, b_n0 = (c0 & 15) << 3;
    const int b_r1 = c1 >> 4, b_n1 = (c1 & 15) << 3;

    float acc[2][8][4];
#pragma unroll
    for (int i = 0; i < 2; i++)
#pragma unroll
        for (int j = 0; j < 8; j++)
#pragma unroll
            for (int k = 0; k < 4; k++) acc[i][j][k] = 0.f;

    unsigned as_base = (unsigned)__cvta_generic_to_shared(&As[0][0]);
    unsigned bs_base = (unsigned)__cvta_generic_to_shared(&Bs[0][0]);

    uint4 va0, va1, vb0, vb1;
    va0 = *(const uint4*)(Ag + (long long)a_r0 * MD + a_k0);
    va1 = *(const uint4*)(Ag + (long long)a_r1 * MD + a_k1);
    vb0 = *(const uint4*)(Bg + (long long)b_r0 * HI + b_n0);
    vb1 = *(const uint4*)(Bg + (long long)b_r1 * HI + b_n1);
    *(uint4*)(&As[a_r0][a_k0]) = va0;
    *(uint4*)(&As[a_r1][a_k1]) = va1;
    *(uint4*)(&Bs[b_r0][b_n0]) = vb0;
    *(uint4*)(&Bs[b_r1][b_n1]) = vb1;
    __syncthreads();

    const int KT = HO / 32;  // 32
    for (int kt = 0; kt < KT; kt++) {
        if (kt + 1 < KT) {
            va0 = *(const uint4*)(Ag + (long long)a_r0 * MD + (kt + 1) * 32 + a_k0);
            va1 = *(const uint4*)(Ag + (long long)a_r1 * MD + (kt + 1) * 32 + a_k1);
            vb0 = *(const uint4*)(Bg + (long long)((kt + 1) * 32 + b_r0) * HI + b_n0);
            vb1 = *(const uint4*)(Bg + (long long)((kt + 1) * 32 + b_r1) * HI + b_n1);
        }
#pragma unroll
        for (int ks = 0; ks < 2; ks++) {
            unsigned af[2][4];
#pragma unroll
            for (int mi = 0; mi < 2; mi++) {
                unsigned addr = as_base +
                    (((wm * 32 + mi * 16 + (lane & 15)) * 40 + ks * 16 + ((lane >> 4) << 3)) << 1);
                ldsm4(af[mi][0], af[mi][1], af[mi][2], af[mi][3], addr);
            }
            unsigned bf[8][2];
#pragma unroll
            for (int nj = 0; nj < 4; nj++) {
                unsigned addr = bs_base +
                    (((ks * 16 + (lane & 15)) * 136 + wn * 64 + nj * 16 + ((lane >> 4) << 3)) << 1);
                unsigned t0, t1, t2, t3;
                ldsm4t(t0, t1, t2, t3, addr);
                bf[nj * 2][0] = t0; bf[nj * 2][1] = t1;
                bf[nj * 2 + 1][0] = t2; bf[nj * 2 + 1][1] = t3;
            }
#pragma unroll
            for (int mi = 0; mi < 2; mi++)
#pragma unroll
                for (int ni = 0; ni < 8; ni++)
                    mma16816(acc[mi][ni], af[mi], bf[ni]);
        }
        __syncthreads();
        if (kt + 1 < KT) {
            *(uint4*)(&As[a_r0][a_k0]) = va0;
            *(uint4*)(&As[a_r1][a_k1]) = va1;
            *(uint4*)(&Bs[b_r0][b_n0]) = vb0;
            *(uint4*)(&Bs[b_r1][b_n1]) = vb1;
            __syncthreads();
        }
    }

    // Epilogue: +b_down[j] then scatter to out[:, perm[j]]
    const int g = lane >> 2, t = lane & 3;
#pragma unroll
    for (int mi = 0; mi < 2; mi++) {
#pragma unroll
        for (int ni = 0; ni < 8; ni++) {
            int r  = r0 + wm * 32 + mi * 16 + g;
            int jj = h * HI + n0 + wn * 64 + ni * 8 + t * 2;
            int p  = __ldg(perm + jj);
            float bd0 = __ldg(b_down + jj);
            float bd1 = __ldg(b_down + jj + 1);
            float2 o0; o0.x = acc[mi][ni][0] + bd0; o0.y = acc[mi][ni][1] + bd1;
            *(float2*)(out + (long long)r * FD + p) = o0;
            float2 o1; o1.x = acc[mi][ni][2] + bd0; o1.y = acc[mi][ni][3] + bd1;
            *(float2*)(out + (long long)(r + 8) * FD + p) = o1;
        }
    }
}

extern "C" void kernel_launch(void* const* d_in, const int* in_sizes, int n_in,
                              void* d_out, int out_size) {
    const float* x      = (const float*)d_in[0];
    const int*   perm   = (const int*)d_in[1];
    const float* w_up   = (const float*)d_in[2];
    const float* b_up   = (const float*)d_in[3];
    const float* w_down = (const float*)d_in[4];
    const float* b_down = (const float*)d_in[5];
    float* out = (float*)d_out;

    k_prep_x<<<(NB * FD / 4 + 255) / 256, 256>>>(x, perm);
    k_prep_w<<<(NH * HI * HO / 4 + 255) / 256, 256>>>(w_up, w_down);

    dim3 g1(NH * 8, NB / 128);   // (128, 64)
    k_up<<<g1, 256>>>(b_up);

    dim3 g2(NH * 2, NB / 128);   // (32, 64)
    k_down<<<g2, 256>>>(perm, b_down, out);
}

// round 8
// speedup vs baseline: 1.7445x; 1.7445x over previous
#include <cuda_runtime.h>
#include <cuda_fp16.h>

#define NB 8192
#define FD 4096
#define NH 16
#define HI 256
#define HO 1024
#define MD 16384

// Scratch (device globals — no allocation in kernel_launch)
__device__ __half g_xperm[NB * FD];                 // 64 MB
__device__ __half g_w1[NH * HI * HO];               // 8 MB
__device__ __half g_w2[NH * HO * HI];               // 8 MB
__device__ __half g_h[(long long)NB * MD];          // 256 MB

__device__ __forceinline__ float gelu_f(float v) {
    return 0.5f * v * (1.0f + erff(v * 0.7071067811865476f));
}

__device__ __forceinline__ void ldsm4(unsigned &r0, unsigned &r1, unsigned &r2, unsigned &r3, unsigned addr) {
    asm volatile("ldmatrix.sync.aligned.m8n8.x4.shared.b16 {%0,%1,%2,%3},[%4];"
                 : "=r"(r0), "=r"(r1), "=r"(r2), "=r"(r3) : "r"(addr));
}
__device__ __forceinline__ void ldsm4t(unsigned &r0, unsigned &r1, unsigned &r2, unsigned &r3, unsigned addr) {
    asm volatile("ldmatrix.sync.aligned.m8n8.x4.trans.shared.b16 {%0,%1,%2,%3},[%4];"
                 : "=r"(r0), "=r"(r1), "=r"(r2), "=r"(r3) : "r"(addr));
}
__device__ __forceinline__ void mma16816(float c[4], const unsigned a[4], const unsigned b[2]) {
    asm volatile("mma.sync.aligned.m16n8k16.row.col.f32.f16.f16.f32 "
                 "{%0,%1,%2,%3},{%4,%5,%6,%7},{%8,%9},{%0,%1,%2,%3};"
                 : "+f"(c[0]), "+f"(c[1]), "+f"(c[2]), "+f"(c[3])
                 : "r"(a[0]), "r"(a[1]), "r"(a[2]), "r"(a[3]), "r"(b[0]), "r"(b[1]));
}

#define CP16(s, g) asm volatile("cp.async.cg.shared.global [%0], [%1], 16;\n" :: "r"(s), "l"(g))

// ---------------------------------------------------------------------------
// Prep kernels
// ---------------------------------------------------------------------------
__global__ void __launch_bounds__(256) k_prep_x(const float* __restrict__ x,
                                                const int* __restrict__ perm) {
    int i = blockIdx.x * 256 + threadIdx.x;
    if (i >= NB * FD / 4) return;
    int b  = i >> 10;
    int k4 = (i & 1023) << 2;
    int p  = __ldg(perm + k4);
    const float4 v = *(const float4*)(x + (long long)b * FD + p);
    __half2* dst = (__half2*)(g_xperm + (long long)b * FD + k4);
    dst[0] = __floats2half2_rn(v.x, v.y);
    dst[1] = __floats2half2_rn(v.z, v.w);
}

__global__ void __launch_bounds__(256) k_prep_w(const float* __restrict__ wu,
                                                const float* __restrict__ wd) {
    int i = blockIdx.x * 256 + threadIdx.x;
    const int N4 = NH * HI * HO / 4;
    if (i >= N4) return;
    float4 a = *(const float4*)(wu + (long long)i * 4);
    __half2* d1 = (__half2*)(g_w1 + (long long)i * 4);
    d1[0] = __floats2half2_rn(a.x, a.y);
    d1[1] = __floats2half2_rn(a.z, a.w);
    float4 b = *(const float4*)(wd + (long long)i * 4);
    __half2* d2 = (__half2*)(g_w2 + (long long)i * 4);
    d2[0] = __floats2half2_rn(b.x, b.y);
    d2[1] = __floats2half2_rn(b.z, b.w);
}

// ---------------------------------------------------------------------------
// Unified GEMM: BM=128, BN=128, BK=64, 8 warps (4x2), 3-stage cp.async,
// XOR-swizzled smem (conflict-free ldmatrix), fused epilogue.
//   EPI=0: H = gelu(Xperm @ W1 + b_up)   -> g_h (fp16)
//   EPI=1: out[:, perm[j]] = H @ W2 + b_down  (fp32 scatter)
// ---------------------------------------------------------------------------
template<int KT, int NT_BITS, int LDA, int LDB, int EPI>
__global__ void __launch_bounds__(256, 2) gemm_k(const float* __restrict__ bias,
                                                 const int* __restrict__ perm,
                                                 float* __restrict__ out) {
    extern __shared__ char smem[];
    constexpr int ASTG = 128 * 128;   // bytes per A stage
    constexpr int BSTG = 64 * 256;    // bytes per B stage
    constexpr int AHEAD = KT * 64;    // K = per-head A width
    const unsigned sAb = (unsigned)__cvta_generic_to_shared(smem);
    const unsigned sBb = sAb + 3 * ASTG;

    const int h  = blockIdx.x >> NT_BITS;
    const int nt = blockIdx.x & ((1 << NT_BITS) - 1);
    const int r0 = blockIdx.y << 7;
    const int n0 = nt << 7;
    const int tid = threadIdx.x;
    const int lane = tid & 31, warp = tid >> 5;
    const int wm = warp & 3, wn = warp >> 2;

    const __half* Abase = (EPI == 0) ? g_xperm : g_h;
    const __half* Bbase = (EPI == 0) ? g_w1 : g_w2;
    const __half* Ag = Abase + (long long)r0 * LDA + h * AHEAD;
    const __half* Bg = Bbase + (long long)h * AHEAD * LDB + n0;

    auto load_stage = [&](int stage, int kt) {
        unsigned sa = sAb + stage * ASTG;
        unsigned sb = sBb + stage * BSTG;
        const __half* Agk = Ag + kt * 64;
        const __half* Bgk = Bg + (long long)kt * 64 * LDB;
#pragma unroll
        for (int i = 0; i < 4; i++) {
            int c = tid + i * 256;
            int m = c >> 3, k16 = c & 7;
            CP16(sa + m * 128 + ((k16 ^ (m & 7)) << 4),
                 Agk + (long long)m * LDA + k16 * 8);
        }
#pragma unroll
        for (int i = 0; i < 4; i++) {
            int c = tid + i * 256;
            int k = c >> 4, cn = c & 15;
            CP16(sb + k * 256 + ((cn ^ ((k & 7) << 1)) << 4),
                 Bgk + (long long)k * LDB + cn * 8);
        }
        asm volatile("cp.async.commit_group;\n");
    };

    float acc[2][8][4] = {};

    load_stage(0, 0);

    for (int kt = 0; kt < KT; kt++) {
        if (kt + 1 < KT) {
            load_stage((kt + 1) % 3, kt + 1);
            asm volatile("cp.async.wait_group 1;\n");
        } else {
            asm volatile("cp.async.wait_group 0;\n");
        }
        __syncthreads();
        const int stg = kt % 3;
        const unsigned sa = sAb + stg * ASTG;
        const unsigned sb = sBb + stg * BSTG;
#pragma unroll
        for (int ks = 0; ks < 4; ks++) {
            unsigned af[2][4];
#pragma unroll
            for (int mi = 0; mi < 2; mi++) {
                int m = wm * 32 + mi * 16 + (lane & 15);
                int k16 = ks * 2 + (lane >> 4);
                ldsm4(af[mi][0], af[mi][1], af[mi][2], af[mi][3],
                      sa + m * 128 + ((k16 ^ (m & 7)) << 4));
            }
            unsigned bf[8][2];
#pragma unroll
            for (int nj = 0; nj < 4; nj++) {
                int k = ks * 16 + (lane & 15);
                int cn = wn * 8 + nj * 2 + (lane >> 4);
                unsigned t0, t1, t2, t3;
                ldsm4t(t0, t1, t2, t3,
                       sb + k * 256 + ((cn ^ ((k & 7) << 1)) << 4));
                bf[nj * 2][0] = t0; bf[nj * 2][1] = t1;
                bf[nj * 2 + 1][0] = t2; bf[nj * 2 + 1][1] = t3;
            }
#pragma unroll
            for (int mi = 0; mi < 2; mi++)
#pragma unroll
                for (int ni = 0; ni < 8; ni++)
                    mma16816(acc[mi][ni], af[mi], bf[ni]);
        }
        // No trailing sync needed: next iter writes stage (kt+2)%3, and the
        // slowest possible concurrent reader is stage kt-1 -> (kt+2)-(kt-1)=3,
        // but issue happens at iter kt+1 targeting (kt+2)%3 vs lagging compute
        // (kt)%3: differ by 2 mod 3 -> disjoint buffers.
    }

    // Epilogue
    const int g = lane >> 2, t = lane & 3;
    const int cb = h * LDB + n0;   // column base in head-concat space
#pragma unroll
    for (int mi = 0; mi < 2; mi++) {
#pragma unroll
        for (int ni = 0; ni < 8; ni++) {
            int r = r0 + wm * 32 + mi * 16 + g;
            int c = cb + wn * 64 + ni * 8 + t * 2;
            float b0 = __ldg(bias + c), b1 = __ldg(bias + c + 1);
            if (EPI == 0) {
                float v0 = gelu_f(acc[mi][ni][0] + b0);
                float v1 = gelu_f(acc[mi][ni][1] + b1);
                *(__half2*)(g_h + (long long)r * MD + c) = __floats2half2_rn(v0, v1);
                v0 = gelu_f(acc[mi][ni][2] + b0);
                v1 = gelu_f(acc[mi][ni][3] + b1);
                *(__half2*)(g_h + (long long)(r + 8) * MD + c) = __floats2half2_rn(v0, v1);
            } else {
                int p = __ldg(perm + c);   // perm chunk structure: c even -> perm[c+1]=perm[c]+1
                float2 o0; o0.x = acc[mi][ni][0] + b0; o0.y = acc[mi][ni][1] + b1;
                *(float2*)(out + (long long)r * FD + p) = o0;
                float2 o1; o1.x = acc[mi][ni][2] + b0; o1.y = acc[mi][ni][3] + b1;
                *(float2*)(out + (long long)(r + 8) * FD + p) = o1;
            }
        }
    }
}

extern "C" void kernel_launch(void* const* d_in, const int* in_sizes, int n_in,
                              void* d_out, int out_size) {
    const float* x      = (const float*)d_in[0];
    const int*   perm   = (const int*)d_in[1];
    const float* w_up   = (const float*)d_in[2];
    const float* b_up   = (const float*)d_in[3];
    const float* w_down = (const float*)d_in[4];
    const float* b_down = (const float*)d_in[5];
    float* out = (float*)d_out;

    k_prep_x<<<(NB * FD / 4 + 255) / 256, 256>>>(x, perm);
    k_prep_w<<<(NH * HI * HO / 4 + 255) / 256, 256>>>(w_up, w_down);

    constexpr int SMEM = 3 * (128 * 128 + 64 * 256);   // 98304 bytes
    cudaFuncSetAttribute(gemm_k<4, 3, FD, HO, 0>,
                         cudaFuncAttributeMaxDynamicSharedMemorySize, SMEM);
    cudaFuncSetAttribute(gemm_k<16, 1, MD, HI, 1>,
                         cudaFuncAttributeMaxDynamicSharedMemorySize, SMEM);

    dim3 g1(NH * 8, NB / 128);   // (128, 64) tiles: K=256
    gemm_k<4, 3, FD, HO, 0><<<g1, 256, SMEM>>>(b_up, perm, (float*)nullptr);

    dim3 g2(NH * 2, NB / 128);   // (32, 64) tiles: K=1024
    gemm_k<16, 1, MD, HI, 1><<<g2, 256, SMEM>>>(b_down, perm, out);
}